// round 2
// baseline (speedup 1.0000x reference)
#include <cuda_runtime.h>

#define Hh 192
#define Wd 192
#define HW (Hh*Wd)
#define Nb 6
#define KG 20
#define KC 400
#define NA 403          // 400 ctrl + 3 affine
#define SA 408          // padded row stride (cols 403,404 = rhs, 405..407 = zero pad)
#define NB 8            // LU panel width
#define LAMBDc 100.0f
#define BIGc 100000000.0f
#define EPSc 1e-9f
#define STEPc (2.0f/191.0f)

// round(linspace(0,191,20)) — data independent
__device__ __constant__ int c_ctrl[KG] =
    {0,10,20,30,40,50,60,70,80,90,101,111,121,131,141,151,161,171,181,191};

// ------- scratch (device globals, no allocs) -------
__device__ float g_cx[Nb*HW];
__device__ float g_cy[Nb*HW];
__device__ float g_dx[Nb*HW];
__device__ float g_dy[Nb*HW];
__device__ float g_m [Nb*HW];
__device__ __align__(16) float g_A[Nb][NA][SA];   // ~3.95 MB, L2 resident
__device__ __align__(16) float4 g_cw[Nb][KC];     // (sx, sy, w0, w1)
__device__ float g_aff[Nb][6];                    // sol[400+r][c] at [r*2+c]

// ============================================================
// Kernel 1: fused analytic-field backward warp
// ============================================================
__global__ void k_prepare(const float* __restrict__ duv,
                          const float* __restrict__ uv,
                          float* __restrict__ out_mask)
{
    int idx = blockIdx.x*blockDim.x + threadIdx.x;
    if (idx >= Nb*HW) return;

    float gx = uv[idx*2+0];
    float gy = uv[idx*2+1];
    float x = (gx + 1.0f)*0.5f*(Wd-1);
    float y = (gy + 1.0f)*0.5f*(Hh-1);
    float x0f = floorf(x), y0f = floorf(y);
    float wx = x - x0f,   wy = y - y0f;
    int x0 = (int)x0f, y0 = (int)y0f;

    float acx=0.f, acy=0.f, adx=0.f, ady=0.f, am=0.f;

    #pragma unroll
    for (int cyi = 0; cyi < 2; cyi++) {
        #pragma unroll
        for (int cxi = 0; cxi < 2; cxi++) {
            int xi = x0 + cxi, yi = y0 + cyi;
            float w = (cxi ? wx : 1.0f-wx) * (cyi ? wy : 1.0f-wy);
            if (xi >= 0 && xi < Wd && yi >= 0 && yi < Hh) {
                float du0 = duv[(yi*Wd+xi)*2+0];
                float du1 = duv[(yi*Wd+xi)*2+1];
                float vpix = (fabsf(du0) <= 1.0f && fabsf(du1) <= 1.0f) ? 1.0f : 0.0f;
                float bx = xi*STEPc - 1.0f;
                float by = yi*STEPc - 1.0f;
                acx += w*bx;
                acy += w*by;
                adx += w*(du0-bx)*vpix;
                ady += w*(du1-by)*vpix;
                am  += w*vpix;
            }
        }
    }
    float mth = (am > 0.5f) ? 1.0f : 0.0f;
    g_cx[idx]=acx; g_cy[idx]=acy; g_dx[idx]=adx; g_dy[idx]=ady; g_m[idx]=mth;
    out_mask[idx] = mth;   // mask_ output (N,1,H,W)
}

// ============================================================
// Kernel 2: build + blocked LU (partial pivoting) + back-sub, one CTA/batch
// ============================================================
__global__ void __launch_bounds__(1024, 1) k_solve()
{
    const int n   = blockIdx.x;
    const int tid = threadIdx.x;
    float* A = &g_A[n][0][0];

    __shared__ float2 sSrc[KC];
    __shared__ float  sM[KC];
    __shared__ __align__(16) float sP[NA][NB];   // panel (multipliers)
    __shared__ __align__(16) float sU[NB][SA];   // U strip
    __shared__ float sSol[NA][2];
    __shared__ int   sPivIdx;
    __shared__ float sXb[2];

    // ---- gather src / m at control pixels ----
    if (tid < KC) {
        int a = tid / KG, b = tid % KG;
        int pix = c_ctrl[a]*Wd + c_ctrl[b];
        sSrc[tid] = make_float2(g_cx[n*HW+pix], g_cy[n*HW+pix]);
        sM[tid]   = g_m[n*HW+pix];
    }
    __syncthreads();

    // ---- build augmented matrix ----
    for (int idx = tid; idx < NA*SA; idx += 1024) {
        int i = idx / SA, j = idx - i*SA;
        float v = 0.0f;
        if (j < 405) {
            if (i < KC) {
                float2 si = sSrc[i];
                if (j < KC) {
                    float2 sj = sSrc[j];
                    float ddx = si.x - sj.x, ddy = si.y - sj.y;
                    float r2 = ddx*ddx + ddy*ddy;
                    v = 0.5f * r2 * __logf(r2 + EPSc);
                    if (i == j) v += LAMBDc + BIGc*(1.0f - sM[i]);
                } else if (j == 400) v = 1.0f;
                else if (j == 401) v = si.x;
                else if (j == 402) v = si.y;
                else if (j == 403) v = c_ctrl[i % KG]*STEPc - 1.0f;  // dst.x
                else               v = c_ctrl[i / KG]*STEPc - 1.0f;  // dst.y
            } else {
                int r = i - KC;
                if (j < KC) {
                    float2 sj = sSrc[j];
                    v = (r == 0) ? 1.0f : (r == 1 ? sj.x : sj.y);
                }
            }
        }
        A[idx] = v;
    }
    __syncthreads();

    // ---- blocked LU with partial pivoting ----
    for (int kb = 0; kb < NA; kb += NB) {
        int ke = min(kb+NB, NA);
        int bw = ke - kb;
        int nact = NA - kb;
        int Lw = 405 - ke;
        int Lp = (Lw + 3) & ~3;   // padded trailing width (pad cols are zero)

        // load panel columns into SMEM
        for (int idx = tid; idx < nact*bw; idx += 1024) {
            int t = idx / bw, s = idx - t*bw;
            sP[t][s] = A[(kb+t)*SA + kb + s];
        }
        __syncthreads();

        // panel factorization
        for (int s = 0; s < bw; s++) {
            if (tid < 32) {
                float best = -1.0f; int bi = s;
                for (int t = s + tid; t < nact; t += 32) {
                    float v = fabsf(sP[t][s]);
                    if (v > best) { best = v; bi = t; }
                }
                #pragma unroll
                for (int off = 16; off; off >>= 1) {
                    float ov = __shfl_down_sync(0xffffffffu, best, off);
                    int   oi = __shfl_down_sync(0xffffffffu, bi,   off);
                    if (ov > best) { best = ov; bi = oi; }
                }
                if (tid == 0) sPivIdx = bi;
            }
            __syncthreads();
            int p = sPivIdx;
            if (p != s) {
                if (tid < bw) { float t0 = sP[s][tid]; sP[s][tid] = sP[p][tid]; sP[p][tid] = t0; }
                for (int j = tid; j < Lp; j += 1024) {
                    float t1 = A[(kb+s)*SA + ke + j];
                    A[(kb+s)*SA + ke + j] = A[(kb+p)*SA + ke + j];
                    A[(kb+p)*SA + ke + j] = t1;
                }
            }
            __syncthreads();
            float inv = 1.0f / sP[s][s];
            for (int t = s + 1 + tid; t < nact; t += 1024) {
                float f = sP[t][s] * inv;
                sP[t][s] = f;
                #pragma unroll
                for (int j = 0; j < NB; j++)
                    if (j > s && j < bw) sP[t][j] -= f * sP[s][j];
            }
            __syncthreads();
        }

        // write back U11 (upper bw x bw) — needed for back substitution
        for (int idx = tid; idx < bw*bw; idx += 1024) {
            int t = idx / bw, s = idx - t*bw;
            A[(kb+t)*SA + kb + s] = sP[t][s];
        }

        // load U strip (rows kb..ke-1, cols ke..), TRSM by L11 (column-parallel, no sync)
        for (int idx = tid; idx < bw*Lp; idx += 1024) {
            int r = idx / Lp, j = idx - r*Lp;
            sU[r][j] = A[(kb+r)*SA + ke + j];
        }
        __syncthreads();
        for (int j = tid; j < Lp; j += 1024) {
            float col[NB];
            #pragma unroll
            for (int r = 0; r < NB; r++) col[r] = (r < bw) ? sU[r][j] : 0.0f;
            #pragma unroll
            for (int r = 1; r < NB; r++)
                if (r < bw) {
                    #pragma unroll
                    for (int s2 = 0; s2 < NB; s2++)
                        if (s2 < r) col[r] -= sP[r][s2]*col[s2];
                }
            #pragma unroll
            for (int r = 0; r < NB; r++) if (r < bw) sU[r][j] = col[r];
        }
        __syncthreads();
        // write back U strip
        for (int idx = tid; idx < bw*Lp; idx += 1024) {
            int r = idx / Lp, j = idx - r*Lp;
            A[(kb+r)*SA + ke + j] = sU[r][j];
        }

        // rank-8 trailing update, 2x4 register tiles (only reached when bw==8)
        int nrows = NA - ke;
        if (nrows > 0) {
            int nrt = (nrows + 1) >> 1;
            int nc4 = Lp >> 2;
            for (int tile = tid; tile < nrt*nc4; tile += 1024) {
                int tr = tile / nc4, tc = tile - tr*nc4;
                int i0 = ke + 2*tr;
                int j0 = 4*tc;
                bool two = (i0 + 1 < NA);
                float F0[NB], F1[NB];
                #pragma unroll
                for (int s = 0; s < NB; s++) {
                    F0[s] = sP[i0-kb][s];
                    F1[s] = two ? sP[i0+1-kb][s] : 0.0f;
                }
                float4 a0 = *(const float4*)&A[i0*SA + ke + j0];
                float4 a1 = two ? *(const float4*)&A[(i0+1)*SA + ke + j0]
                                : make_float4(0,0,0,0);
                #pragma unroll
                for (int s = 0; s < NB; s++) {
                    float4 u = *(const float4*)&sU[s][j0];
                    a0.x = fmaf(-F0[s], u.x, a0.x);
                    a0.y = fmaf(-F0[s], u.y, a0.y);
                    a0.z = fmaf(-F0[s], u.z, a0.z);
                    a0.w = fmaf(-F0[s], u.w, a0.w);
                    a1.x = fmaf(-F1[s], u.x, a1.x);
                    a1.y = fmaf(-F1[s], u.y, a1.y);
                    a1.z = fmaf(-F1[s], u.z, a1.z);
                    a1.w = fmaf(-F1[s], u.w, a1.w);
                }
                *(float4*)&A[i0*SA + ke + j0] = a0;
                if (two) *(float4*)&A[(i0+1)*SA + ke + j0] = a1;
            }
        }
        __syncthreads();
    }

    // ---- back substitution (2 rhs columns at 403,404) ----
    for (int k = NA-1; k >= 0; k--) {
        if (tid == 0) {
            float inv = 1.0f / A[k*SA + k];
            float x0 = A[k*SA + 403]*inv;
            float x1 = A[k*SA + 404]*inv;
            sSol[k][0] = x0; sSol[k][1] = x1;
            sXb[0] = x0; sXb[1] = x1;
        }
        __syncthreads();
        float x0 = sXb[0], x1 = sXb[1];
        for (int i = tid; i < k; i += 1024) {
            float aik = A[i*SA + k];
            A[i*SA + 403] -= aik*x0;
            A[i*SA + 404] -= aik*x1;
        }
        __syncthreads();
    }

    // ---- pack (src, wgt) for eval ----
    if (tid < KC)
        g_cw[n][tid] = make_float4(sSrc[tid].x, sSrc[tid].y, sSol[tid][0], sSol[tid][1]);
    if (tid >= KC && tid < NA) {
        int r = tid - KC;
        g_aff[n][r*2+0] = sSol[tid][0];
        g_aff[n][r*2+1] = sSol[tid][1];
    }
}

// ============================================================
// Kernel 3: fused TPS eval (3 FD queries in one pass) + final compose
// ============================================================
__global__ void __launch_bounds__(256) k_eval(float* __restrict__ out)
{
    __shared__ __align__(16) float4 scw[KC];
    __shared__ float saff[6];

    const int bpn = HW/256;                // 144 blocks per batch
    int n  = blockIdx.x / bpn;
    int p  = (blockIdx.x - n*bpn)*256 + threadIdx.x;

    for (int i = threadIdx.x; i < KC; i += 256) scw[i] = g_cw[n][i];
    if (threadIdx.x < 6) saff[threadIdx.x] = g_aff[n][threadIdx.x];
    __syncthreads();

    int gi = n*HW + p;
    float qx = g_cx[gi], qy = g_cy[gi];
    float m  = g_m[gi];

    const float DX  = STEPc;
    const float DX2 = DX*DX;
    const float TDX = 2.0f*DX;

    float a00=0.f, a01=0.f, ax0=0.f, ax1=0.f, ay0=0.f, ay1=0.f;

    #pragma unroll 4
    for (int c = 0; c < KC; c++) {
        float4 cw = scw[c];
        float ddx = qx - cw.x;
        float ddy = qy - cw.y;
        float r2  = fmaf(ddx, ddx, ddy*ddy);
        float r2x = r2 + fmaf(TDX, ddx, DX2);
        float r2y = r2 + fmaf(TDX, ddy, DX2);
        float u0 = 0.5f*r2 *__logf(r2  + EPSc);
        float ux = 0.5f*r2x*__logf(r2x + EPSc);
        float uy = 0.5f*r2y*__logf(r2y + EPSc);
        a00 = fmaf(u0, cw.z, a00);  a01 = fmaf(u0, cw.w, a01);
        ax0 = fmaf(ux, cw.z, ax0);  ax1 = fmaf(ux, cw.w, ax1);
        ay0 = fmaf(uy, cw.z, ay0);  ay1 = fmaf(uy, cw.w, ay1);
    }

    float qxx = qx + DX, qyy = qy + DX;
    float c00 = a00 + saff[0] + qx *saff[2] + qy *saff[4];
    float c01 = a01 + saff[1] + qx *saff[3] + qy *saff[5];
    float cx0 = ax0 + saff[0] + qxx*saff[2] + qy *saff[4];
    float cx1 = ax1 + saff[1] + qxx*saff[3] + qy *saff[5];
    float cy0 = ay0 + saff[0] + qx *saff[2] + qyy*saff[4];
    float cy1 = ay1 + saff[1] + qx *saff[3] + qyy*saff[5];

    const float invDX = 1.0f/STEPc;
    float av = (cx0 - c00)*invDX;
    float bv = (cx1 - c01)*invDX;
    float cv = (cy0 - c00)*invDX;
    float dv = (cy1 - c01)*invDX;

    float d0 = g_dx[gi], d1 = g_dy[gi];
    float dn0 = av*d0 + cv*d1;
    float dn1 = bv*d0 + dv*d1;

    int w = p % Wd, h = p / Wd;
    float bx = w*STEPc - 1.0f;
    float by = h*STEPc - 1.0f;
    float o0 = (bx + dn0)*m - 2.0f*(1.0f - m);
    float o1 = (by + dn1)*m - 2.0f*(1.0f - m);
    out[gi*2+0] = o0;
    out[gi*2+1] = o1;
}

// ============================================================
extern "C" void kernel_launch(void* const* d_in, const int* in_sizes, int n_in,
                              void* d_out, int out_size)
{
    const float* in0 = (const float*)d_in[0];
    const float* in1 = (const float*)d_in[1];
    const float* duv;
    const float* uv;
    if (in_sizes[0] == 2*HW) { duv = in0; uv = in1; }
    else                     { duv = in1; uv = in0; }

    float* out = (float*)d_out;
    float* out_mask = out + (size_t)Nb*HW*2;   // deform (N,H,W,2) then mask (N,1,H,W)

    k_prepare<<<(Nb*HW + 255)/256, 256>>>(duv, uv, out_mask);
    k_solve<<<Nb, 1024>>>();
    k_eval<<<Nb*(HW/256), 256>>>(out);
}